// round 14
// baseline (speedup 1.0000x reference)
#include <cuda_runtime.h>
#include <cuda_fp16.h>
#include <cstdint>
#include <math.h>

#define BB 2
#define HH 128
#define WW 128
#define HW (HH*WW)
#define DIM 128
#define NH 8
#define HD 16

#define CPAD 160            // unified channel count (147 used, padded)
#define PW 130              // padded image width/height
#define NPIX (PW*PW)

// ---------------- device scratch (allocation-free rule) ----------------
__device__ __align__(16) __half g_XTh[BB * NPIX * CPAD];  // padded fp16 activations [pix][ch-permuted]
__device__ __align__(16) __half g_WUh[5 * 45 * 4096];     // fragment-ordered fp16 conv weights
__device__ __align__(16) __half g_WPh[2 * 16384];         // fragment-ordered fp16 proj weights
__device__ __align__(16) __half g_ATTh[BB * 2 * HW * 128];// attn out, [b,s][pix][ch-permuted] fp16
__device__ float g_WB[640];                                // conv biases
__device__ float g_OUT[BB * 640 * HW];                     // q | k_pan | v_pan | k_ms | v_ms

// ---------------- helpers ----------------
__device__ __forceinline__ void cp16(uint32_t dst, const void* src) {
    size_t gp;
    asm("cvta.to.global.u64 %0, %1;" : "=l"(gp) : "l"(src));
    asm volatile("cp.async.ca.shared.global [%0], [%1], 16;" :: "r"(dst), "l"(gp));
}

__device__ __forceinline__ void mma_f16(float* c, const uint32_t* a,
                                        uint32_t b0, uint32_t b1) {
    asm volatile(
        "mma.sync.aligned.m16n8k16.row.col.f32.f16.f16.f32 "
        "{%0,%1,%2,%3}, {%4,%5,%6,%7}, {%8,%9}, {%0,%1,%2,%3};"
        : "+f"(c[0]), "+f"(c[1]), "+f"(c[2]), "+f"(c[3])
        : "r"(a[0]), "r"(a[1]), "r"(a[2]), "r"(a[3]), "r"(b0), "r"(b1));
}

// ---------------------------------------------------------------------------
// build_xt: transpose x + derived channels into padded [pix][ch] fp16 layout.
// ---------------------------------------------------------------------------
__global__ __launch_bounds__(256) void build_xt_kernel(
    const float* __restrict__ x, const float* __restrict__ ms,
    const float* __restrict__ lpan, const float* __restrict__ pan,
    const float* __restrict__ s)
{
    __shared__ float st[CPAD][65];
    int b  = blockIdx.y;
    int p0 = blockIdx.x * 64;
    int t  = threadIdx.x;
    float sv = s[b];

    for (int i = t; i < CPAD * 64; i += 256) {
        int c = i >> 6, px = i & 63;
        int p = p0 + px;
        float v = 0.0f;
        if (c < 128)        v = x[(b * 128 + c) * HW + p];
        else if (c < 136) { float lp = lpan[b * HW + p];
                            float m  = ms[(b * 8 + (c - 128)) * HW + p];
                            v = lp * (1.0f - sv) + m * sv; }
        else if (c == 136)  v = lpan[b * HW + p];
        else if (c == 137)  v = pan[b * HW + p];
        else if (c == 138)  v = pan[b * HW + p] - lpan[b * HW + p];
        else if (c < 147)   v = ms[(b * 8 + (c - 139)) * HW + p];
        st[c][px] = v;
    }
    __syncthreads();
    for (int i = t; i < 64 * 10; i += 256) {
        int px = i / 10, blk = i % 10;
        int p = p0 + px;
        int y = p >> 7, xx = p & 127;
        size_t pidx = (size_t)(y + 1) * PW + (xx + 1);
        __half h[16];
#pragma unroll
        for (int j = 0; j < 16; j++) {
            int pg2 = j >> 2, jj = j & 3;
            int ch = blk * 16 + pg2 * 2 + (jj & 1) + (jj >> 1) * 8;
            h[j] = __float2half(st[ch][px]);
        }
        __half* dst = g_XTh + ((size_t)b * NPIX + pidx) * CPAD + blk * 16;
        *(uint4*)dst       = *(uint4*)h;
        *(uint4*)(dst + 8) = *(uint4*)(h + 8);
    }
}

__global__ void zero_border_kernel()
{
    int idx = blockIdx.x * blockDim.x + threadIdx.x;
    if (idx >= BB * NPIX) return;
    int b = idx / NPIX, p = idx % NPIX;
    int py = p / PW, px = p % PW;
    if (py == 0 || py == PW - 1 || px == 0 || px == PW - 1) {
        uint4 z = {0u, 0u, 0u, 0u};
        uint4* dst = (uint4*)(g_XTh + ((size_t)b * NPIX + p) * CPAD);
#pragma unroll
        for (int i = 0; i < CPAD / 8; i++) dst[i] = z;
    }
}

// ---------------------------------------------------------------------------
// repack conv weights into m16n8k16 fragment order (fp16)
// ---------------------------------------------------------------------------
__global__ void repack_w_kernel(
    const float* __restrict__ qw, const float* __restrict__ kpw,
    const float* __restrict__ vpw, const float* __restrict__ kvw,
    const float* __restrict__ qb, const float* __restrict__ kpb,
    const float* __restrict__ vpb, const float* __restrict__ kvb)
{
    int idx = blockIdx.x * blockDim.x + threadIdx.x;
    if (idx < 640) {
        float bv;
        if (idx < 128)      bv = qb[idx];
        else if (idx < 256) bv = kpb[idx - 128];
        else if (idx < 384) bv = vpb[idx - 256];
        else                bv = kvb[idx - 384];
        g_WB[idx] = bv;
    }
    if (idx >= 5 * 45 * 4096) return;
    int i2 = idx;
    int e     = i2 & 1;  i2 >>= 1;
    int r     = i2 & 3;  i2 >>= 2;
    int lane  = i2 & 31; i2 >>= 5;
    int mfrag = i2 & 7;  i2 >>= 3;
    int k16   = i2 & 1;  i2 >>= 1;
    int step  = i2 % 45;
    int octile = i2 / 45;

    int m_local = mfrag * 16 + (lane >> 2) + (r & 1) * 8;
    int c       = (step % 5) * 32 + k16 * 16 + (lane & 3) * 2 + e + (r >> 1) * 8;
    int tap     = step / 5;
    int oc_g    = octile * 128 + m_local;

    float v = 0.0f;
    if (oc_g < 128) {
        if (c < 136) v = qw[(oc_g * 136 + c) * 9 + tap];
    } else if (oc_g < 256) {
        int oc = oc_g - 128;
        if (c < 128)       v = kpw[(oc * 129 + c) * 9 + tap];
        else if (c == 136) v = kpw[(oc * 129 + 128) * 9 + tap];
    } else if (oc_g < 384) {
        int oc = oc_g - 256;
        if (c < 128)                  v = vpw[(oc * 131 + c) * 9 + tap];
        else if (c >= 136 && c < 139) v = vpw[(oc * 131 + 128 + (c - 136)) * 9 + tap];
    } else {
        int oc = oc_g - 384;
        if (c < 128)                  v = kvw[(oc * 136 + c) * 9 + tap];
        else if (c >= 139 && c < 147) v = kvw[(oc * 136 + 128 + (c - 139)) * 9 + tap];
    }
    g_WUh[idx] = __float2half(v);
}

// ---------------------------------------------------------------------------
// repack proj weights (128x128 each) into same A-fragment order
// ---------------------------------------------------------------------------
__global__ void repack_proj_kernel(const float* __restrict__ pw,
                                   const float* __restrict__ mw)
{
    int idx = blockIdx.x * blockDim.x + threadIdx.x;
    if (idx >= 2 * 16384) return;
    int s  = idx >> 14;
    int i2 = idx & 16383;
    int e    = i2 & 1;
    int r    = (i2 >> 1) & 3;
    int lane = (i2 >> 3) & 31;
    int mf   = (i2 >> 8) & 7;
    int k16  = i2 >> 11;
    int m = mf * 16 + (lane >> 2) + (r & 1) * 8;
    int c = k16 * 16 + (lane & 3) * 2 + e + (r >> 1) * 8;
    const float* src = s ? mw : pw;
    g_WPh[idx] = __float2half(src[m * 128 + c]);
}

// ---------------------------------------------------------------------------
// conv via mma.sync m16n8k16 fp16 — PROVEN 487.6us structure (CTA 128x128,
// warp tile 64x32, double buffer). SINGLE CHANGE: launch_bounds(256,3) to
// cap regs at 85 and fit 3 CTAs/SM (occupancy-bound hypothesis).
// ---------------------------------------------------------------------------
#define CONV_SMEM (2 * 16384)
__global__ __launch_bounds__(256, 3) void conv_mma_kernel()
{
    extern __shared__ char smem[];
    int t = threadIdx.x;
    int w = t >> 5, lane = t & 31;
    int g = lane >> 2, tt = lane & 3;
    int y0 = blockIdx.x;
    int octile = blockIdx.y;
    int b = blockIdx.z;

    int mw0 = (w >> 2) * 4;
    int n80 = (w & 3) * 4;

    const __half* XTb = g_XTh + (size_t)b * NPIX * CPAD;
    const __half* WUo = g_WUh + (size_t)octile * 45 * 4096;
    uint32_t sbase = (uint32_t)__cvta_generic_to_shared(smem);

    int pxl = t >> 1, k16s = t & 1;

    float acc[4][4][4];
#pragma unroll
    for (int mf = 0; mf < 4; mf++)
#pragma unroll
        for (int nf = 0; nf < 4; nf++)
#pragma unroll
            for (int r = 0; r < 4; r++) acc[mf][nf][r] = 0.0f;

    auto issue = [&](int step, int stage) {
        uint32_t sA = sbase + stage * 16384;
        uint32_t sB = sA + 8192;
        const char* Ws = (const char*)(WUo + (size_t)step * 4096);
        cp16(sA + t * 32,      Ws + t * 32);
        cp16(sA + t * 32 + 16, Ws + t * 32 + 16);
        int tap = step / 5, kc = (step % 5) * 32;
        int dy = tap / 3 - 1, dx = tap % 3 - 1;
        const char* src = (const char*)(XTb +
            ((size_t)(y0 + dy + 1) * PW + (pxl + dx + 1)) * CPAD + kc + k16s * 16);
        uint32_t d = sB + k16s * 4096 + pxl * 32;
        cp16(d,      src);
        cp16(d + 16, src + 16);
        asm volatile("cp.async.commit_group;" ::: "memory");
    };

    issue(0, 0);
    for (int step = 0; step < 45; step++) {
        int stage = step & 1;
        if (step + 1 < 45) {
            issue(step + 1, stage ^ 1);
            asm volatile("cp.async.wait_group 1;" ::: "memory");
        } else {
            asm volatile("cp.async.wait_group 0;" ::: "memory");
        }
        __syncthreads();

        uint32_t sA = sbase + stage * 16384;
        uint32_t sB = sA + 8192;
#pragma unroll
        for (int k16 = 0; k16 < 2; k16++) {
            uint32_t a[4][4];
#pragma unroll
            for (int mf = 0; mf < 4; mf++) {
                uint32_t addr = sA + k16 * 4096 + (mw0 + mf) * 512 + lane * 16;
                asm volatile("ld.shared.v4.u32 {%0,%1,%2,%3}, [%4];"
                    : "=r"(a[mf][0]), "=r"(a[mf][1]), "=r"(a[mf][2]), "=r"(a[mf][3])
                    : "r"(addr));
            }
            uint32_t b0[4], b1[4];
#pragma unroll
            for (int nf = 0; nf < 4; nf++) {
                uint32_t addr = sB + k16 * 4096 +
                                (((n80 + nf) * 8 + g) * 32) + tt * 8;
                asm volatile("ld.shared.v2.u32 {%0,%1}, [%2];"
                    : "=r"(b0[nf]), "=r"(b1[nf]) : "r"(addr));
            }
#pragma unroll
            for (int mf = 0; mf < 4; mf++)
#pragma unroll
                for (int nf = 0; nf < 4; nf++)
                    mma_f16(acc[mf][nf], a[mf], b0[nf], b1[nf]);
        }
        __syncthreads();
    }

    float scale = (octile == 0) ? 0.25f : 1.0f;
#pragma unroll
    for (int mf = 0; mf < 4; mf++) {
        int oc = octile * 128 + (mw0 + mf) * 16 + g;
        float b0v = g_WB[oc];
        float b1v = g_WB[oc + 8];
        float* r0 = g_OUT + (size_t)(b * 640 + oc) * HW + y0 * WW;
        float* r1 = r0 + (size_t)8 * HW;
#pragma unroll
        for (int nf = 0; nf < 4; nf++) {
            int n = (n80 + nf) * 8 + tt * 2;
            float2 o0, o1;
            o0.x = (acc[mf][nf][0] + b0v) * scale;
            o0.y = (acc[mf][nf][1] + b0v) * scale;
            o1.x = (acc[mf][nf][2] + b1v) * scale;
            o1.y = (acc[mf][nf][3] + b1v) * scale;
            *(float2*)(r0 + n) = o0;
            *(float2*)(r1 + n) = o1;
        }
    }
}

// ---------------------------------------------------------------------------
// attn v3 (PROVEN 487.6us config): 32x32 tile, 2x2 px/thread,
// 8 channels staged per sync.
// ---------------------------------------------------------------------------
__global__ __launch_bounds__(256) void attn_kernel(const float* __restrict__ dep_w,
                                                   const float* __restrict__ dep_b)
{
    __shared__ float s_dw[144][9];
    __shared__ float s_db[144];
    __shared__ float s_tile[8][34][36];

    int b    = blockIdx.z;
    int sn   = blockIdx.y;
    int sidx = sn >> 3, n = sn & 7;
    int tY   = (blockIdx.x >> 2) * 32;
    int tX   = (blockIdx.x & 3) * 32;
    int t    = threadIdx.x;
    int ty   = t >> 4, tx = t & 15;
    int py0  = tY + 2 * ty, px0 = tX + 2 * tx;

    for (int i = t; i < 144 * 9; i += 256) s_dw[i / 9][i % 9] = dep_w[i];
    if (t < 144) s_db[t] = dep_b[t];

    int kbase = (sidx == 0 ? 128 : 384) + n * 16;
    int vbase = kbase + 128;
    const float* Ob = g_OUT + (size_t)b * 640 * HW;

    float logit[4][9];
#pragma unroll
    for (int p = 0; p < 4; p++)
#pragma unroll
        for (int a = 0; a < 9; a++) logit[p][a] = 0.0f;

    // ---- phase K: logits (2 batches of 8 channels)
    for (int batch = 0; batch < 2; batch++) {
        __syncthreads();
#pragma unroll
        for (int dd = 0; dd < 8; dd++) {
            const float* P = Ob + (size_t)(kbase + batch * 8 + dd) * HW;
            for (int i = t; i < 34 * 34; i += 256) {
                int r = i / 34, c = i % 34;
                int yy = tY - 1 + r, xx = tX - 1 + c;
                float v = 0.0f;
                if (yy >= 0 && yy < HH && xx >= 0 && xx < WW) v = P[yy * WW + xx];
                s_tile[dd][r][c] = v;
            }
        }
        __syncthreads();
#pragma unroll 2
        for (int dd = 0; dd < 8; dd++) {
            int d = batch * 8 + dd;
            float tap[4][4];
#pragma unroll
            for (int yy = 0; yy < 4; yy++)
#pragma unroll
                for (int xx = 0; xx < 4; xx++)
                    tap[yy][xx] = s_tile[dd][2 * ty + yy][2 * tx + xx];
            const float* Pq = Ob + (size_t)(n * 16 + d) * HW + py0 * WW + px0;
            float qv[4] = {Pq[0], Pq[1], Pq[WW], Pq[WW + 1]};
#pragma unroll
            for (int a = 0; a < 9; a++) {
                const float* wp = s_dw[d * 9 + a];
                float w9[9];
#pragma unroll
                for (int k = 0; k < 9; k++) w9[k] = wp[k];
                float bsv = s_db[d * 9 + a];
#pragma unroll
                for (int p = 0; p < 4; p++) {
                    int oy = p >> 1, ox = p & 1;
                    float kda = bsv;
#pragma unroll
                    for (int ky = 0; ky < 3; ky++)
#pragma unroll
                        for (int kx = 0; kx < 3; kx++)
                            kda += w9[ky * 3 + kx] * tap[oy + ky][ox + kx];
                    logit[p][a] += qv[p] * kda;
                }
            }
        }
    }

    // ---- softmax
    float attnv[4][9];
#pragma unroll
    for (int p = 0; p < 4; p++) {
        float m = logit[p][0];
#pragma unroll
        for (int a = 1; a < 9; a++) m = fmaxf(m, logit[p][a]);
        float sum = 0.0f;
#pragma unroll
        for (int a = 0; a < 9; a++) { attnv[p][a] = __expf(logit[p][a] - m); sum += attnv[p][a]; }
        float inv = 1.0f / sum;
#pragma unroll
        for (int a = 0; a < 9; a++) attnv[p][a] *= inv;
    }

    // ---- phase V (2 batches of 8 channels)
    __half oh[4][16];
    for (int batch = 0; batch < 2; batch++) {
        __syncthreads();
#pragma unroll
        for (int dd = 0; dd < 8; dd++) {
            const float* P = Ob + (size_t)(vbase + batch * 8 + dd) * HW;
            for (int i = t; i < 34 * 34; i += 256) {
                int r = i / 34, c = i % 34;
                int yy = tY - 1 + r, xx = tX - 1 + c;
                float v = 0.0f;
                if (yy >= 0 && yy < HH && xx >= 0 && xx < WW) v = P[yy * WW + xx];
                s_tile[dd][r][c] = v;
            }
        }
        __syncthreads();
#pragma unroll 2
        for (int dd = 0; dd < 8; dd++) {
            int d = batch * 8 + dd;
            float tap[4][4];
#pragma unroll
            for (int yy = 0; yy < 4; yy++)
#pragma unroll
                for (int xx = 0; xx < 4; xx++)
                    tap[yy][xx] = s_tile[dd][2 * ty + yy][2 * tx + xx];
            float outv[4] = {0.f, 0.f, 0.f, 0.f};
#pragma unroll
            for (int a = 0; a < 9; a++) {
                const float* wp = s_dw[d * 9 + a];
                float w9[9];
#pragma unroll
                for (int k = 0; k < 9; k++) w9[k] = wp[k];
                float bsv = s_db[d * 9 + a];
#pragma unroll
                for (int p = 0; p < 4; p++) {
                    int oy = p >> 1, ox = p & 1;
                    float vda = bsv;
#pragma unroll
                    for (int ky = 0; ky < 3; ky++)
#pragma unroll
                        for (int kx = 0; kx < 3; kx++)
                            vda += w9[ky * 3 + kx] * tap[oy + ky][ox + kx];
                    outv[p] += attnv[p][a] * vda;
                }
            }
            const int h2 = d >> 3, rem = d & 7;
            const int j  = (rem >> 1) * 4 + h2 * 2 + (rem & 1);
#pragma unroll
            for (int p = 0; p < 4; p++) oh[p][j] = __float2half(outv[p]);
        }
    }

    __half* Adst = g_ATTh + (size_t)(b * 2 + sidx) * HW * 128;
#pragma unroll
    for (int p = 0; p < 4; p++) {
        int pix = (py0 + (p >> 1)) * WW + px0 + (p & 1);
        __half* dst = Adst + (size_t)pix * 128 + n * 16;
        *(uint4*)dst       = *(uint4*)&oh[p][0];
        *(uint4*)(dst + 8) = *(uint4*)&oh[p][8];
    }
}

// ---------------------------------------------------------------------------
// proj via mma: CTA = 128 oc x 128 px (one row), K=128. Writes d_out.
// ---------------------------------------------------------------------------
#define PROJ_SMEM 65536
__global__ __launch_bounds__(256) void proj_mma_kernel(
    const float* __restrict__ ppan_b, const float* __restrict__ pms_b,
    float* __restrict__ out)
{
    extern __shared__ char psm[];
    int t = threadIdx.x, w = t >> 5, lane = t & 31;
    int g = lane >> 2, tt = lane & 3;
    int mw0 = (w >> 2) * 4, n80 = (w & 3) * 4;
    int row = blockIdx.x, sidx = blockIdx.y, b = blockIdx.z;
    uint32_t sb = (uint32_t)__cvta_generic_to_shared(psm);

    const char* Asrc = (const char*)(g_WPh + (size_t)sidx * 16384);
#pragma unroll
    for (int j = 0; j < 8; j++) cp16(sb + t * 128 + j * 16, Asrc + t * 128 + j * 16);
    {
        int px = t >> 1;
        int kh = (t & 1) * 4;
        const char* Bsrc = (const char*)(g_ATTh +
            ((size_t)(b * 2 + sidx) * HW + row * 128 + px) * 128);
#pragma unroll
        for (int k16 = 0; k16 < 4; k16++) {
            uint32_t d = sb + 32768 + (kh + k16) * 4096 + px * 32;
            cp16(d,      Bsrc + (kh + k16) * 32);
            cp16(d + 16, Bsrc + (kh + k16) * 32 + 16);
        }
    }
    asm volatile("cp.async.commit_group;" ::: "memory");
    asm volatile("cp.async.wait_group 0;" ::: "memory");
    __syncthreads();

    float acc[4][4][4];
#pragma unroll
    for (int mf = 0; mf < 4; mf++)
#pragma unroll
        for (int nf = 0; nf < 4; nf++)
#pragma unroll
            for (int r = 0; r < 4; r++) acc[mf][nf][r] = 0.0f;

#pragma unroll
    for (int k16 = 0; k16 < 8; k16++) {
        uint32_t a[4][4];
#pragma unroll
        for (int mf = 0; mf < 4; mf++) {
            uint32_t addr = sb + k16 * 4096 + (mw0 + mf) * 512 + lane * 16;
            asm volatile("ld.shared.v4.u32 {%0,%1,%2,%3}, [%4];"
                : "=r"(a[mf][0]), "=r"(a[mf][1]), "=r"(a[mf][2]), "=r"(a[mf][3])
                : "r"(addr));
        }
        uint32_t b0[4], b1[4];
#pragma unroll
        for (int nf = 0; nf < 4; nf++) {
            uint32_t addr = sb + 32768 + k16 * 4096 + (((n80 + nf) * 8 + g) * 32) + tt * 8;
            asm volatile("ld.shared.v2.u32 {%0,%1}, [%2];"
                : "=r"(b0[nf]), "=r"(b1[nf]) : "r"(addr));
        }
#pragma unroll
        for (int mf = 0; mf < 4; mf++)
#pragma unroll
            for (int nf = 0; nf < 4; nf++)
                mma_f16(acc[mf][nf], a[mf], b0[nf], b1[nf]);
    }

    const float* bp = sidx ? pms_b : ppan_b;
    float* obase = out + (size_t)sidx * BB * DIM * HW;
#pragma unroll
    for (int mf = 0; mf < 4; mf++) {
        int oc = (mw0 + mf) * 16 + g;
        float b0v = bp[oc];
        float b1v = bp[oc + 8];
        float* r0 = obase + ((size_t)(b * DIM + oc)) * HW + row * WW;
        float* r1 = r0 + (size_t)8 * HW;
#pragma unroll
        for (int nf = 0; nf < 4; nf++) {
            int nn = (n80 + nf) * 8 + tt * 2;
            float2 o0, o1;
            o0.x = acc[mf][nf][0] + b0v;
            o0.y = acc[mf][nf][1] + b0v;
            o1.x = acc[mf][nf][2] + b1v;
            o1.y = acc[mf][nf][3] + b1v;
            *(float2*)(r0 + nn) = o0;
            *(float2*)(r1 + nn) = o1;
        }
    }
}

// ---------------------------------------------------------------------------
extern "C" void kernel_launch(void* const* d_in, const int* in_sizes, int n_in,
                              void* d_out, int out_size)
{
    const float* x        = (const float*)d_in[0];
    const float* ms       = (const float*)d_in[1];
    const float* lpan     = (const float*)d_in[2];
    const float* pan      = (const float*)d_in[3];
    const float* s        = (const float*)d_in[4];
    const float* q_w      = (const float*)d_in[5];
    const float* q_b      = (const float*)d_in[6];
    const float* k_pan_w  = (const float*)d_in[7];
    const float* k_pan_b  = (const float*)d_in[8];
    const float* v_pan_w  = (const float*)d_in[9];
    const float* v_pan_b  = (const float*)d_in[10];
    const float* kv_ms_w  = (const float*)d_in[11];
    const float* kv_ms_b  = (const float*)d_in[12];
    const float* dep_w    = (const float*)d_in[13];
    const float* dep_b    = (const float*)d_in[14];
    const float* ppan_w   = (const float*)d_in[15];
    const float* ppan_b   = (const float*)d_in[16];
    const float* pms_w    = (const float*)d_in[17];
    const float* pms_b    = (const float*)d_in[18];
    float* out = (float*)d_out;

    cudaFuncSetAttribute(conv_mma_kernel,
                         cudaFuncAttributeMaxDynamicSharedMemorySize, CONV_SMEM);
    cudaFuncSetAttribute(proj_mma_kernel,
                         cudaFuncAttributeMaxDynamicSharedMemorySize, PROJ_SMEM);

    dim3 xg(HW / 64, BB);
    build_xt_kernel<<<xg, 256>>>(x, ms, lpan, pan, s);
    zero_border_kernel<<<(BB * NPIX + 255) / 256, 256>>>();
    repack_w_kernel<<<(5 * 45 * 4096 + 255) / 256, 256>>>(
        q_w, k_pan_w, v_pan_w, kv_ms_w, q_b, k_pan_b, v_pan_b, kv_ms_b);
    repack_proj_kernel<<<(2 * 16384 + 255) / 256, 256>>>(ppan_w, pms_w);

    dim3 cg(HH, 5, BB);
    conv_mma_kernel<<<cg, 256, CONV_SMEM>>>();

    dim3 ag(16, 16, BB);
    attn_kernel<<<ag, 256>>>(dep_w, dep_b);

    dim3 pj(HH, 2, BB);
    proj_mma_kernel<<<pj, 256, PROJ_SMEM>>>(ppan_b, pms_b, out);
}

// round 15
// speedup vs baseline: 1.2090x; 1.2090x over previous
#include <cuda_runtime.h>
#include <cuda_fp16.h>
#include <cstdint>
#include <math.h>

#define BB 2
#define HH 128
#define WW 128
#define HW (HH*WW)
#define DIM 128
#define NH 8
#define HD 16

#define CPAD 160            // unified channel count (147 used, padded)
#define PW 130              // padded image width/height
#define NPIX (PW*PW)

// prep_kernel flat ranges
#define PREP_PROJ   (2 * 16384)
#define PREP_W      (5 * 45 * 4096)
#define PREP_BORDER (BB * NPIX)
#define PREP_TOTAL  (PREP_PROJ + PREP_W + PREP_BORDER)

// ---------------- device scratch (allocation-free rule) ----------------
__device__ __align__(16) __half g_XTh[BB * NPIX * CPAD];  // padded fp16 activations [pix][ch-permuted]
__device__ __align__(16) __half g_WUh[5 * 45 * 4096];     // fragment-ordered fp16 conv weights
__device__ __align__(16) __half g_WPh[2 * 16384];         // fragment-ordered fp16 proj weights
__device__ __align__(16) __half g_ATTh[BB * 2 * HW * 128];// attn out, [b,s][pix][ch-permuted] fp16
__device__ float g_WB[640];                                // conv biases
__device__ float g_OUT[BB * 640 * HW];                     // q | k_pan | v_pan | k_ms | v_ms

// ---------------- helpers ----------------
__device__ __forceinline__ void cp16(uint32_t dst, const void* src) {
    size_t gp;
    asm("cvta.to.global.u64 %0, %1;" : "=l"(gp) : "l"(src));
    asm volatile("cp.async.ca.shared.global [%0], [%1], 16;" :: "r"(dst), "l"(gp));
}

__device__ __forceinline__ void mma_f16(float* c, const uint32_t* a,
                                        uint32_t b0, uint32_t b1) {
    asm volatile(
        "mma.sync.aligned.m16n8k16.row.col.f32.f16.f16.f32 "
        "{%0,%1,%2,%3}, {%4,%5,%6,%7}, {%8,%9}, {%0,%1,%2,%3};"
        : "+f"(c[0]), "+f"(c[1]), "+f"(c[2]), "+f"(c[3])
        : "r"(a[0]), "r"(a[1]), "r"(a[2]), "r"(a[3]), "r"(b0), "r"(b1));
}

// ---------------------------------------------------------------------------
// build_xt: transpose x + derived channels into padded [pix][ch] fp16 layout.
// ---------------------------------------------------------------------------
__global__ __launch_bounds__(256) void build_xt_kernel(
    const float* __restrict__ x, const float* __restrict__ ms,
    const float* __restrict__ lpan, const float* __restrict__ pan,
    const float* __restrict__ s)
{
    __shared__ float st[CPAD][65];
    int b  = blockIdx.y;
    int p0 = blockIdx.x * 64;
    int t  = threadIdx.x;
    float sv = s[b];

    for (int i = t; i < CPAD * 64; i += 256) {
        int c = i >> 6, px = i & 63;
        int p = p0 + px;
        float v = 0.0f;
        if (c < 128)        v = x[(b * 128 + c) * HW + p];
        else if (c < 136) { float lp = lpan[b * HW + p];
                            float m  = ms[(b * 8 + (c - 128)) * HW + p];
                            v = lp * (1.0f - sv) + m * sv; }
        else if (c == 136)  v = lpan[b * HW + p];
        else if (c == 137)  v = pan[b * HW + p];
        else if (c == 138)  v = pan[b * HW + p] - lpan[b * HW + p];
        else if (c < 147)   v = ms[(b * 8 + (c - 139)) * HW + p];
        st[c][px] = v;
    }
    __syncthreads();
    for (int i = t; i < 64 * 10; i += 256) {
        int px = i / 10, blk = i % 10;
        int p = p0 + px;
        int y = p >> 7, xx = p & 127;
        size_t pidx = (size_t)(y + 1) * PW + (xx + 1);
        __half h[16];
#pragma unroll
        for (int j = 0; j < 16; j++) {
            int pg2 = j >> 2, jj = j & 3;
            int ch = blk * 16 + pg2 * 2 + (jj & 1) + (jj >> 1) * 8;
            h[j] = __float2half(st[ch][px]);
        }
        __half* dst = g_XTh + ((size_t)b * NPIX + pidx) * CPAD + blk * 16;
        *(uint4*)dst       = *(uint4*)h;
        *(uint4*)(dst + 8) = *(uint4*)(h + 8);
    }
}

// ---------------------------------------------------------------------------
// prep_kernel: fused repack_proj + repack_w(+bias) + zero_border.
// Flat index over three disjoint ranges; all workloads independent.
// ---------------------------------------------------------------------------
__global__ void prep_kernel(
    const float* __restrict__ qw, const float* __restrict__ kpw,
    const float* __restrict__ vpw, const float* __restrict__ kvw,
    const float* __restrict__ qb, const float* __restrict__ kpb,
    const float* __restrict__ vpb, const float* __restrict__ kvb,
    const float* __restrict__ ppw, const float* __restrict__ pmw)
{
    int gidx = blockIdx.x * blockDim.x + threadIdx.x;

    if (gidx < PREP_PROJ) {
        // ---- repack proj weights into A-fragment order
        int idx = gidx;
        int s  = idx >> 14;
        int i2 = idx & 16383;
        int e    = i2 & 1;
        int r    = (i2 >> 1) & 3;
        int lane = (i2 >> 3) & 31;
        int mf   = (i2 >> 8) & 7;
        int k16  = i2 >> 11;
        int m = mf * 16 + (lane >> 2) + (r & 1) * 8;
        int c = k16 * 16 + (lane & 3) * 2 + e + (r >> 1) * 8;
        const float* src = s ? pmw : ppw;
        g_WPh[idx] = __float2half(src[m * 128 + c]);
        return;
    }
    gidx -= PREP_PROJ;

    if (gidx < PREP_W) {
        int idx = gidx;
        if (idx < 640) {
            float bv;
            if (idx < 128)      bv = qb[idx];
            else if (idx < 256) bv = kpb[idx - 128];
            else if (idx < 384) bv = vpb[idx - 256];
            else                bv = kvb[idx - 384];
            g_WB[idx] = bv;
        }
        int i2 = idx;
        int e     = i2 & 1;  i2 >>= 1;
        int r     = i2 & 3;  i2 >>= 2;
        int lane  = i2 & 31; i2 >>= 5;
        int mfrag = i2 & 7;  i2 >>= 3;
        int k16   = i2 & 1;  i2 >>= 1;
        int step  = i2 % 45;
        int octile = i2 / 45;

        int m_local = mfrag * 16 + (lane >> 2) + (r & 1) * 8;
        int c       = (step % 5) * 32 + k16 * 16 + (lane & 3) * 2 + e + (r >> 1) * 8;
        int tap     = step / 5;
        int oc_g    = octile * 128 + m_local;

        float v = 0.0f;
        if (oc_g < 128) {
            if (c < 136) v = qw[(oc_g * 136 + c) * 9 + tap];
        } else if (oc_g < 256) {
            int oc = oc_g - 128;
            if (c < 128)       v = kpw[(oc * 129 + c) * 9 + tap];
            else if (c == 136) v = kpw[(oc * 129 + 128) * 9 + tap];
        } else if (oc_g < 384) {
            int oc = oc_g - 256;
            if (c < 128)                  v = vpw[(oc * 131 + c) * 9 + tap];
            else if (c >= 136 && c < 139) v = vpw[(oc * 131 + 128 + (c - 136)) * 9 + tap];
        } else {
            int oc = oc_g - 384;
            if (c < 128)                  v = kvw[(oc * 136 + c) * 9 + tap];
            else if (c >= 139 && c < 147) v = kvw[(oc * 136 + 128 + (c - 139)) * 9 + tap];
        }
        g_WUh[idx] = __float2half(v);
        return;
    }
    gidx -= PREP_W;

    if (gidx < PREP_BORDER) {
        int b = gidx / NPIX, p = gidx % NPIX;
        int py = p / PW, px = p % PW;
        if (py == 0 || py == PW - 1 || px == 0 || px == PW - 1) {
            uint4 z = {0u, 0u, 0u, 0u};
            uint4* dst = (uint4*)(g_XTh + ((size_t)b * NPIX + p) * CPAD);
#pragma unroll
            for (int i = 0; i < CPAD / 8; i++) dst[i] = z;
        }
    }
}

// ---------------------------------------------------------------------------
// conv via mma.sync m16n8k16 fp16 — PROVEN 487.6us config: CTA 128x128,
// warp tile 64x32, cp.async.ca double buffer. UNCHANGED.
// ---------------------------------------------------------------------------
#define CONV_SMEM (2 * 16384)
__global__ __launch_bounds__(256) void conv_mma_kernel()
{
    extern __shared__ char smem[];
    int t = threadIdx.x;
    int w = t >> 5, lane = t & 31;
    int g = lane >> 2, tt = lane & 3;
    int y0 = blockIdx.x;
    int octile = blockIdx.y;
    int b = blockIdx.z;

    int mw0 = (w >> 2) * 4;
    int n80 = (w & 3) * 4;

    const __half* XTb = g_XTh + (size_t)b * NPIX * CPAD;
    const __half* WUo = g_WUh + (size_t)octile * 45 * 4096;
    uint32_t sbase = (uint32_t)__cvta_generic_to_shared(smem);

    int pxl = t >> 1, k16s = t & 1;

    float acc[4][4][4];
#pragma unroll
    for (int mf = 0; mf < 4; mf++)
#pragma unroll
        for (int nf = 0; nf < 4; nf++)
#pragma unroll
            for (int r = 0; r < 4; r++) acc[mf][nf][r] = 0.0f;

    auto issue = [&](int step, int stage) {
        uint32_t sA = sbase + stage * 16384;
        uint32_t sB = sA + 8192;
        const char* Ws = (const char*)(WUo + (size_t)step * 4096);
        cp16(sA + t * 32,      Ws + t * 32);
        cp16(sA + t * 32 + 16, Ws + t * 32 + 16);
        int tap = step / 5, kc = (step % 5) * 32;
        int dy = tap / 3 - 1, dx = tap % 3 - 1;
        const char* src = (const char*)(XTb +
            ((size_t)(y0 + dy + 1) * PW + (pxl + dx + 1)) * CPAD + kc + k16s * 16);
        uint32_t d = sB + k16s * 4096 + pxl * 32;
        cp16(d,      src);
        cp16(d + 16, src + 16);
        asm volatile("cp.async.commit_group;" ::: "memory");
    };

    issue(0, 0);
    for (int step = 0; step < 45; step++) {
        int stage = step & 1;
        if (step + 1 < 45) {
            issue(step + 1, stage ^ 1);
            asm volatile("cp.async.wait_group 1;" ::: "memory");
        } else {
            asm volatile("cp.async.wait_group 0;" ::: "memory");
        }
        __syncthreads();

        uint32_t sA = sbase + stage * 16384;
        uint32_t sB = sA + 8192;
#pragma unroll
        for (int k16 = 0; k16 < 2; k16++) {
            uint32_t a[4][4];
#pragma unroll
            for (int mf = 0; mf < 4; mf++) {
                uint32_t addr = sA + k16 * 4096 + (mw0 + mf) * 512 + lane * 16;
                asm volatile("ld.shared.v4.u32 {%0,%1,%2,%3}, [%4];"
                    : "=r"(a[mf][0]), "=r"(a[mf][1]), "=r"(a[mf][2]), "=r"(a[mf][3])
                    : "r"(addr));
            }
            uint32_t b0[4], b1[4];
#pragma unroll
            for (int nf = 0; nf < 4; nf++) {
                uint32_t addr = sB + k16 * 4096 +
                                (((n80 + nf) * 8 + g) * 32) + tt * 8;
                asm volatile("ld.shared.v2.u32 {%0,%1}, [%2];"
                    : "=r"(b0[nf]), "=r"(b1[nf]) : "r"(addr));
            }
#pragma unroll
            for (int mf = 0; mf < 4; mf++)
#pragma unroll
                for (int nf = 0; nf < 4; nf++)
                    mma_f16(acc[mf][nf], a[mf], b0[nf], b1[nf]);
        }
        __syncthreads();
    }

    float scale = (octile == 0) ? 0.25f : 1.0f;
#pragma unroll
    for (int mf = 0; mf < 4; mf++) {
        int oc = octile * 128 + (mw0 + mf) * 16 + g;
        float b0v = g_WB[oc];
        float b1v = g_WB[oc + 8];
        float* r0 = g_OUT + (size_t)(b * 640 + oc) * HW + y0 * WW;
        float* r1 = r0 + (size_t)8 * HW;
#pragma unroll
        for (int nf = 0; nf < 4; nf++) {
            int n = (n80 + nf) * 8 + tt * 2;
            float2 o0, o1;
            o0.x = (acc[mf][nf][0] + b0v) * scale;
            o0.y = (acc[mf][nf][1] + b0v) * scale;
            o1.x = (acc[mf][nf][2] + b1v) * scale;
            o1.y = (acc[mf][nf][3] + b1v) * scale;
            *(float2*)(r0 + n) = o0;
            *(float2*)(r1 + n) = o1;
        }
    }
}

// ---------------------------------------------------------------------------
// attn v3 (PROVEN 487.6us config): 32x32 tile, 2x2 px/thread,
// 8 channels staged per sync. UNCHANGED.
// ---------------------------------------------------------------------------
__global__ __launch_bounds__(256) void attn_kernel(const float* __restrict__ dep_w,
                                                   const float* __restrict__ dep_b)
{
    __shared__ float s_dw[144][9];
    __shared__ float s_db[144];
    __shared__ float s_tile[8][34][36];

    int b    = blockIdx.z;
    int sn   = blockIdx.y;
    int sidx = sn >> 3, n = sn & 7;
    int tY   = (blockIdx.x >> 2) * 32;
    int tX   = (blockIdx.x & 3) * 32;
    int t    = threadIdx.x;
    int ty   = t >> 4, tx = t & 15;
    int py0  = tY + 2 * ty, px0 = tX + 2 * tx;

    for (int i = t; i < 144 * 9; i += 256) s_dw[i / 9][i % 9] = dep_w[i];
    if (t < 144) s_db[t] = dep_b[t];

    int kbase = (sidx == 0 ? 128 : 384) + n * 16;
    int vbase = kbase + 128;
    const float* Ob = g_OUT + (size_t)b * 640 * HW;

    float logit[4][9];
#pragma unroll
    for (int p = 0; p < 4; p++)
#pragma unroll
        for (int a = 0; a < 9; a++) logit[p][a] = 0.0f;

    // ---- phase K: logits (2 batches of 8 channels)
    for (int batch = 0; batch < 2; batch++) {
        __syncthreads();
#pragma unroll
        for (int dd = 0; dd < 8; dd++) {
            const float* P = Ob + (size_t)(kbase + batch * 8 + dd) * HW;
            for (int i = t; i < 34 * 34; i += 256) {
                int r = i / 34, c = i % 34;
                int yy = tY - 1 + r, xx = tX - 1 + c;
                float v = 0.0f;
                if (yy >= 0 && yy < HH && xx >= 0 && xx < WW) v = P[yy * WW + xx];
                s_tile[dd][r][c] = v;
            }
        }
        __syncthreads();
#pragma unroll 2
        for (int dd = 0; dd < 8; dd++) {
            int d = batch * 8 + dd;
            float tap[4][4];
#pragma unroll
            for (int yy = 0; yy < 4; yy++)
#pragma unroll
                for (int xx = 0; xx < 4; xx++)
                    tap[yy][xx] = s_tile[dd][2 * ty + yy][2 * tx + xx];
            const float* Pq = Ob + (size_t)(n * 16 + d) * HW + py0 * WW + px0;
            float qv[4] = {Pq[0], Pq[1], Pq[WW], Pq[WW + 1]};
#pragma unroll
            for (int a = 0; a < 9; a++) {
                const float* wp = s_dw[d * 9 + a];
                float w9[9];
#pragma unroll
                for (int k = 0; k < 9; k++) w9[k] = wp[k];
                float bsv = s_db[d * 9 + a];
#pragma unroll
                for (int p = 0; p < 4; p++) {
                    int oy = p >> 1, ox = p & 1;
                    float kda = bsv;
#pragma unroll
                    for (int ky = 0; ky < 3; ky++)
#pragma unroll
                        for (int kx = 0; kx < 3; kx++)
                            kda += w9[ky * 3 + kx] * tap[oy + ky][ox + kx];
                    logit[p][a] += qv[p] * kda;
                }
            }
        }
    }

    // ---- softmax
    float attnv[4][9];
#pragma unroll
    for (int p = 0; p < 4; p++) {
        float m = logit[p][0];
#pragma unroll
        for (int a = 1; a < 9; a++) m = fmaxf(m, logit[p][a]);
        float sum = 0.0f;
#pragma unroll
        for (int a = 0; a < 9; a++) { attnv[p][a] = __expf(logit[p][a] - m); sum += attnv[p][a]; }
        float inv = 1.0f / sum;
#pragma unroll
        for (int a = 0; a < 9; a++) attnv[p][a] *= inv;
    }

    // ---- phase V (2 batches of 8 channels)
    __half oh[4][16];
    for (int batch = 0; batch < 2; batch++) {
        __syncthreads();
#pragma unroll
        for (int dd = 0; dd < 8; dd++) {
            const float* P = Ob + (size_t)(vbase + batch * 8 + dd) * HW;
            for (int i = t; i < 34 * 34; i += 256) {
                int r = i / 34, c = i % 34;
                int yy = tY - 1 + r, xx = tX - 1 + c;
                float v = 0.0f;
                if (yy >= 0 && yy < HH && xx >= 0 && xx < WW) v = P[yy * WW + xx];
                s_tile[dd][r][c] = v;
            }
        }
        __syncthreads();
#pragma unroll 2
        for (int dd = 0; dd < 8; dd++) {
            int d = batch * 8 + dd;
            float tap[4][4];
#pragma unroll
            for (int yy = 0; yy < 4; yy++)
#pragma unroll
                for (int xx = 0; xx < 4; xx++)
                    tap[yy][xx] = s_tile[dd][2 * ty + yy][2 * tx + xx];
            float outv[4] = {0.f, 0.f, 0.f, 0.f};
#pragma unroll
            for (int a = 0; a < 9; a++) {
                const float* wp = s_dw[d * 9 + a];
                float w9[9];
#pragma unroll
                for (int k = 0; k < 9; k++) w9[k] = wp[k];
                float bsv = s_db[d * 9 + a];
#pragma unroll
                for (int p = 0; p < 4; p++) {
                    int oy = p >> 1, ox = p & 1;
                    float vda = bsv;
#pragma unroll
                    for (int ky = 0; ky < 3; ky++)
#pragma unroll
                        for (int kx = 0; kx < 3; kx++)
                            vda += w9[ky * 3 + kx] * tap[oy + ky][ox + kx];
                    outv[p] += attnv[p][a] * vda;
                }
            }
            const int h2 = d >> 3, rem = d & 7;
            const int j  = (rem >> 1) * 4 + h2 * 2 + (rem & 1);
#pragma unroll
            for (int p = 0; p < 4; p++) oh[p][j] = __float2half(outv[p]);
        }
    }

    __half* Adst = g_ATTh + (size_t)(b * 2 + sidx) * HW * 128;
#pragma unroll
    for (int p = 0; p < 4; p++) {
        int pix = (py0 + (p >> 1)) * WW + px0 + (p & 1);
        __half* dst = Adst + (size_t)pix * 128 + n * 16;
        *(uint4*)dst       = *(uint4*)&oh[p][0];
        *(uint4*)(dst + 8) = *(uint4*)&oh[p][8];
    }
}

// ---------------------------------------------------------------------------
// proj via mma: CTA = 128 oc x 128 px (one row), K=128. Writes d_out. UNCHANGED.
// ---------------------------------------------------------------------------
#define PROJ_SMEM 65536
__global__ __launch_bounds__(256) void proj_mma_kernel(
    const float* __restrict__ ppan_b, const float* __restrict__ pms_b,
    float* __restrict__ out)
{
    extern __shared__ char psm[];
    int t = threadIdx.x, w = t >> 5, lane = t & 31;
    int g = lane >> 2, tt = lane & 3;
    int mw0 = (w >> 2) * 4, n80 = (w & 3) * 4;
    int row = blockIdx.x, sidx = blockIdx.y, b = blockIdx.z;
    uint32_t sb = (uint32_t)__cvta_generic_to_shared(psm);

    const char* Asrc = (const char*)(g_WPh + (size_t)sidx * 16384);
#pragma unroll
    for (int j = 0; j < 8; j++) cp16(sb + t * 128 + j * 16, Asrc + t * 128 + j * 16);
    {
        int px = t >> 1;
        int kh = (t & 1) * 4;
        const char* Bsrc = (const char*)(g_ATTh +
            ((size_t)(b * 2 + sidx) * HW + row * 128 + px) * 128);
#pragma unroll
        for (int k16 = 0; k16 < 4; k16++) {
            uint32_t d = sb + 32768 + (kh + k16) * 4096 + px * 32;
            cp16(d,      Bsrc + (kh + k16) * 32);
            cp16(d + 16, Bsrc + (kh + k16) * 32 + 16);
        }
    }
    asm volatile("cp.async.commit_group;" ::: "memory");
    asm volatile("cp.async.wait_group 0;" ::: "memory");
    __syncthreads();

    float acc[4][4][4];
#pragma unroll
    for (int mf = 0; mf < 4; mf++)
#pragma unroll
        for (int nf = 0; nf < 4; nf++)
#pragma unroll
            for (int r = 0; r < 4; r++) acc[mf][nf][r] = 0.0f;

#pragma unroll
    for (int k16 = 0; k16 < 8; k16++) {
        uint32_t a[4][4];
#pragma unroll
        for (int mf = 0; mf < 4; mf++) {
            uint32_t addr = sb + k16 * 4096 + (mw0 + mf) * 512 + lane * 16;
            asm volatile("ld.shared.v4.u32 {%0,%1,%2,%3}, [%4];"
                : "=r"(a[mf][0]), "=r"(a[mf][1]), "=r"(a[mf][2]), "=r"(a[mf][3])
                : "r"(addr));
        }
        uint32_t b0[4], b1[4];
#pragma unroll
        for (int nf = 0; nf < 4; nf++) {
            uint32_t addr = sb + 32768 + k16 * 4096 + (((n80 + nf) * 8 + g) * 32) + tt * 8;
            asm volatile("ld.shared.v2.u32 {%0,%1}, [%2];"
                : "=r"(b0[nf]), "=r"(b1[nf]) : "r"(addr));
        }
#pragma unroll
        for (int mf = 0; mf < 4; mf++)
#pragma unroll
            for (int nf = 0; nf < 4; nf++)
                mma_f16(acc[mf][nf], a[mf], b0[nf], b1[nf]);
    }

    const float* bp = sidx ? pms_b : ppan_b;
    float* obase = out + (size_t)sidx * BB * DIM * HW;
#pragma unroll
    for (int mf = 0; mf < 4; mf++) {
        int oc = (mw0 + mf) * 16 + g;
        float b0v = bp[oc];
        float b1v = bp[oc + 8];
        float* r0 = obase + ((size_t)(b * DIM + oc)) * HW + row * WW;
        float* r1 = r0 + (size_t)8 * HW;
#pragma unroll
        for (int nf = 0; nf < 4; nf++) {
            int nn = (n80 + nf) * 8 + tt * 2;
            float2 o0, o1;
            o0.x = acc[mf][nf][0] + b0v;
            o0.y = acc[mf][nf][1] + b0v;
            o1.x = acc[mf][nf][2] + b1v;
            o1.y = acc[mf][nf][3] + b1v;
            *(float2*)(r0 + nn) = o0;
            *(float2*)(r1 + nn) = o1;
        }
    }
}

// ---------------------------------------------------------------------------
extern "C" void kernel_launch(void* const* d_in, const int* in_sizes, int n_in,
                              void* d_out, int out_size)
{
    const float* x        = (const float*)d_in[0];
    const float* ms       = (const float*)d_in[1];
    const float* lpan     = (const float*)d_in[2];
    const float* pan      = (const float*)d_in[3];
    const float* s        = (const float*)d_in[4];
    const float* q_w      = (const float*)d_in[5];
    const float* q_b      = (const float*)d_in[6];
    const float* k_pan_w  = (const float*)d_in[7];
    const float* k_pan_b  = (const float*)d_in[8];
    const float* v_pan_w  = (const float*)d_in[9];
    const float* v_pan_b  = (const float*)d_in[10];
    const float* kv_ms_w  = (const float*)d_in[11];
    const float* kv_ms_b  = (const float*)d_in[12];
    const float* dep_w    = (const float*)d_in[13];
    const float* dep_b    = (const float*)d_in[14];
    const float* ppan_w   = (const float*)d_in[15];
    const float* ppan_b   = (const float*)d_in[16];
    const float* pms_w    = (const float*)d_in[17];
    const float* pms_b    = (const float*)d_in[18];
    float* out = (float*)d_out;

    cudaFuncSetAttribute(conv_mma_kernel,
                         cudaFuncAttributeMaxDynamicSharedMemorySize, CONV_SMEM);
    cudaFuncSetAttribute(proj_mma_kernel,
                         cudaFuncAttributeMaxDynamicSharedMemorySize, PROJ_SMEM);

    dim3 xg(HW / 64, BB);
    build_xt_kernel<<<xg, 256>>>(x, ms, lpan, pan, s);
    prep_kernel<<<(PREP_TOTAL + 255) / 256, 256>>>(
        q_w, k_pan_w, v_pan_w, kv_ms_w, q_b, k_pan_b, v_pan_b, kv_ms_b,
        ppan_w, pms_w);

    dim3 cg(HH, 5, BB);
    conv_mma_kernel<<<cg, 256, CONV_SMEM>>>();

    dim3 ag(16, 16, BB);
    attn_kernel<<<ag, 256>>>(dep_w, dep_b);

    dim3 pj(HH, 2, BB);
    proj_mma_kernel<<<pj, 256, PROJ_SMEM>>>(ppan_b, pms_b, out);
}

// round 16
// speedup vs baseline: 1.3648x; 1.1289x over previous
#include <cuda_runtime.h>
#include <cuda_fp16.h>
#include <cstdint>
#include <math.h>

#define BB 2
#define HH 128
#define WW 128
#define HW (HH*WW)
#define DIM 128
#define NH 8
#define HD 16

#define CPAD 160            // unified channel count (147 used, padded)
#define PW 130              // padded image width/height
#define NPIX (PW*PW)

// prep_kernel flat ranges
#define PREP_PROJ   (2 * 16384)
#define PREP_W      (5 * 45 * 4096)
#define PREP_BORDER (BB * NPIX)
#define PREP_TOTAL  (PREP_PROJ + PREP_W + PREP_BORDER)

// ---------------- device scratch (allocation-free rule) ----------------
__device__ __align__(16) __half g_XTh[BB * NPIX * CPAD];  // padded fp16 activations [pix][ch-permuted]
__device__ __align__(16) __half g_WUh[5 * 45 * 4096];     // fragment-ordered fp16 conv weights
__device__ __align__(16) __half g_WPh[2 * 16384];         // fragment-ordered fp16 proj weights
__device__ __align__(16) __half g_ATTh[BB * 2 * HW * 128];// attn out, [b,s][pix][ch-permuted] fp16
__device__ float g_WB[640];                                // conv biases
__device__ float g_OUT[BB * 640 * HW];                     // q | k_pan | v_pan | k_ms | v_ms

// ---------------- helpers ----------------
__device__ __forceinline__ void cp16(uint32_t dst, const void* src) {
    size_t gp;
    asm("cvta.to.global.u64 %0, %1;" : "=l"(gp) : "l"(src));
    asm volatile("cp.async.ca.shared.global [%0], [%1], 16;" :: "r"(dst), "l"(gp));
}

__device__ __forceinline__ void mma_f16(float* c, const uint32_t* a,
                                        uint32_t b0, uint32_t b1) {
    asm volatile(
        "mma.sync.aligned.m16n8k16.row.col.f32.f16.f16.f32 "
        "{%0,%1,%2,%3}, {%4,%5,%6,%7}, {%8,%9}, {%0,%1,%2,%3};"
        : "+f"(c[0]), "+f"(c[1]), "+f"(c[2]), "+f"(c[3])
        : "r"(a[0]), "r"(a[1]), "r"(a[2]), "r"(a[3]), "r"(b0), "r"(b1));
}

// ---------------------------------------------------------------------------
// build_xt: transpose x + derived channels into padded [pix][ch] fp16 layout.
// ---------------------------------------------------------------------------
__global__ __launch_bounds__(256) void build_xt_kernel(
    const float* __restrict__ x, const float* __restrict__ ms,
    const float* __restrict__ lpan, const float* __restrict__ pan,
    const float* __restrict__ s)
{
    __shared__ float st[CPAD][65];
    int b  = blockIdx.y;
    int p0 = blockIdx.x * 64;
    int t  = threadIdx.x;
    float sv = s[b];

    for (int i = t; i < CPAD * 64; i += 256) {
        int c = i >> 6, px = i & 63;
        int p = p0 + px;
        float v = 0.0f;
        if (c < 128)        v = x[(b * 128 + c) * HW + p];
        else if (c < 136) { float lp = lpan[b * HW + p];
                            float m  = ms[(b * 8 + (c - 128)) * HW + p];
                            v = lp * (1.0f - sv) + m * sv; }
        else if (c == 136)  v = lpan[b * HW + p];
        else if (c == 137)  v = pan[b * HW + p];
        else if (c == 138)  v = pan[b * HW + p] - lpan[b * HW + p];
        else if (c < 147)   v = ms[(b * 8 + (c - 139)) * HW + p];
        st[c][px] = v;
    }
    __syncthreads();
    for (int i = t; i < 64 * 10; i += 256) {
        int px = i / 10, blk = i % 10;
        int p = p0 + px;
        int y = p >> 7, xx = p & 127;
        size_t pidx = (size_t)(y + 1) * PW + (xx + 1);
        __half h[16];
#pragma unroll
        for (int j = 0; j < 16; j++) {
            int pg2 = j >> 2, jj = j & 3;
            int ch = blk * 16 + pg2 * 2 + (jj & 1) + (jj >> 1) * 8;
            h[j] = __float2half(st[ch][px]);
        }
        __half* dst = g_XTh + ((size_t)b * NPIX + pidx) * CPAD + blk * 16;
        *(uint4*)dst       = *(uint4*)h;
        *(uint4*)(dst + 8) = *(uint4*)(h + 8);
    }
}

// ---------------------------------------------------------------------------
// prep_kernel: fused repack_proj + repack_w(+bias) + zero_border.
// ---------------------------------------------------------------------------
__global__ void prep_kernel(
    const float* __restrict__ qw, const float* __restrict__ kpw,
    const float* __restrict__ vpw, const float* __restrict__ kvw,
    const float* __restrict__ qb, const float* __restrict__ kpb,
    const float* __restrict__ vpb, const float* __restrict__ kvb,
    const float* __restrict__ ppw, const float* __restrict__ pmw)
{
    int gidx = blockIdx.x * blockDim.x + threadIdx.x;

    if (gidx < PREP_PROJ) {
        int idx = gidx;
        int s  = idx >> 14;
        int i2 = idx & 16383;
        int e    = i2 & 1;
        int r    = (i2 >> 1) & 3;
        int lane = (i2 >> 3) & 31;
        int mf   = (i2 >> 8) & 7;
        int k16  = i2 >> 11;
        int m = mf * 16 + (lane >> 2) + (r & 1) * 8;
        int c = k16 * 16 + (lane & 3) * 2 + e + (r >> 1) * 8;
        const float* src = s ? pmw : ppw;
        g_WPh[idx] = __float2half(src[m * 128 + c]);
        return;
    }
    gidx -= PREP_PROJ;

    if (gidx < PREP_W) {
        int idx = gidx;
        if (idx < 640) {
            float bv;
            if (idx < 128)      bv = qb[idx];
            else if (idx < 256) bv = kpb[idx - 128];
            else if (idx < 384) bv = vpb[idx - 256];
            else                bv = kvb[idx - 384];
            g_WB[idx] = bv;
        }
        int i2 = idx;
        int e     = i2 & 1;  i2 >>= 1;
        int r     = i2 & 3;  i2 >>= 2;
        int lane  = i2 & 31; i2 >>= 5;
        int mfrag = i2 & 7;  i2 >>= 3;
        int k16   = i2 & 1;  i2 >>= 1;
        int step  = i2 % 45;
        int octile = i2 / 45;

        int m_local = mfrag * 16 + (lane >> 2) + (r & 1) * 8;
        int c       = (step % 5) * 32 + k16 * 16 + (lane & 3) * 2 + e + (r >> 1) * 8;
        int tap     = step / 5;
        int oc_g    = octile * 128 + m_local;

        float v = 0.0f;
        if (oc_g < 128) {
            if (c < 136) v = qw[(oc_g * 136 + c) * 9 + tap];
        } else if (oc_g < 256) {
            int oc = oc_g - 128;
            if (c < 128)       v = kpw[(oc * 129 + c) * 9 + tap];
            else if (c == 136) v = kpw[(oc * 129 + 128) * 9 + tap];
        } else if (oc_g < 384) {
            int oc = oc_g - 256;
            if (c < 128)                  v = vpw[(oc * 131 + c) * 9 + tap];
            else if (c >= 136 && c < 139) v = vpw[(oc * 131 + 128 + (c - 136)) * 9 + tap];
        } else {
            int oc = oc_g - 384;
            if (c < 128)                  v = kvw[(oc * 136 + c) * 9 + tap];
            else if (c >= 139 && c < 147) v = kvw[(oc * 136 + 128 + (c - 139)) * 9 + tap];
        }
        g_WUh[idx] = __float2half(v);
        return;
    }
    gidx -= PREP_W;

    if (gidx < PREP_BORDER) {
        int b = gidx / NPIX, p = gidx % NPIX;
        int py = p / PW, px = p % PW;
        if (py == 0 || py == PW - 1 || px == 0 || px == PW - 1) {
            uint4 z = {0u, 0u, 0u, 0u};
            uint4* dst = (uint4*)(g_XTh + ((size_t)b * NPIX + p) * CPAD);
#pragma unroll
            for (int i = 0; i < CPAD / 8; i++) dst[i] = z;
        }
    }
}

// ---------------------------------------------------------------------------
// conv via mma.sync m16n8k16 fp16 — PROVEN config: CTA 128x128,
// warp tile 64x32, cp.async.ca double buffer. UNCHANGED.
// ---------------------------------------------------------------------------
#define CONV_SMEM (2 * 16384)
__global__ __launch_bounds__(256) void conv_mma_kernel()
{
    extern __shared__ char smem[];
    int t = threadIdx.x;
    int w = t >> 5, lane = t & 31;
    int g = lane >> 2, tt = lane & 3;
    int y0 = blockIdx.x;
    int octile = blockIdx.y;
    int b = blockIdx.z;

    int mw0 = (w >> 2) * 4;
    int n80 = (w & 3) * 4;

    const __half* XTb = g_XTh + (size_t)b * NPIX * CPAD;
    const __half* WUo = g_WUh + (size_t)octile * 45 * 4096;
    uint32_t sbase = (uint32_t)__cvta_generic_to_shared(smem);

    int pxl = t >> 1, k16s = t & 1;

    float acc[4][4][4];
#pragma unroll
    for (int mf = 0; mf < 4; mf++)
#pragma unroll
        for (int nf = 0; nf < 4; nf++)
#pragma unroll
            for (int r = 0; r < 4; r++) acc[mf][nf][r] = 0.0f;

    auto issue = [&](int step, int stage) {
        uint32_t sA = sbase + stage * 16384;
        uint32_t sB = sA + 8192;
        const char* Ws = (const char*)(WUo + (size_t)step * 4096);
        cp16(sA + t * 32,      Ws + t * 32);
        cp16(sA + t * 32 + 16, Ws + t * 32 + 16);
        int tap = step / 5, kc = (step % 5) * 32;
        int dy = tap / 3 - 1, dx = tap % 3 - 1;
        const char* src = (const char*)(XTb +
            ((size_t)(y0 + dy + 1) * PW + (pxl + dx + 1)) * CPAD + kc + k16s * 16);
        uint32_t d = sB + k16s * 4096 + pxl * 32;
        cp16(d,      src);
        cp16(d + 16, src + 16);
        asm volatile("cp.async.commit_group;" ::: "memory");
    };

    issue(0, 0);
    for (int step = 0; step < 45; step++) {
        int stage = step & 1;
        if (step + 1 < 45) {
            issue(step + 1, stage ^ 1);
            asm volatile("cp.async.wait_group 1;" ::: "memory");
        } else {
            asm volatile("cp.async.wait_group 0;" ::: "memory");
        }
        __syncthreads();

        uint32_t sA = sbase + stage * 16384;
        uint32_t sB = sA + 8192;
#pragma unroll
        for (int k16 = 0; k16 < 2; k16++) {
            uint32_t a[4][4];
#pragma unroll
            for (int mf = 0; mf < 4; mf++) {
                uint32_t addr = sA + k16 * 4096 + (mw0 + mf) * 512 + lane * 16;
                asm volatile("ld.shared.v4.u32 {%0,%1,%2,%3}, [%4];"
                    : "=r"(a[mf][0]), "=r"(a[mf][1]), "=r"(a[mf][2]), "=r"(a[mf][3])
                    : "r"(addr));
            }
            uint32_t b0[4], b1[4];
#pragma unroll
            for (int nf = 0; nf < 4; nf++) {
                uint32_t addr = sB + k16 * 4096 +
                                (((n80 + nf) * 8 + g) * 32) + tt * 8;
                asm volatile("ld.shared.v2.u32 {%0,%1}, [%2];"
                    : "=r"(b0[nf]), "=r"(b1[nf]) : "r"(addr));
            }
#pragma unroll
            for (int mf = 0; mf < 4; mf++)
#pragma unroll
                for (int nf = 0; nf < 4; nf++)
                    mma_f16(acc[mf][nf], a[mf], b0[nf], b1[nf]);
        }
        __syncthreads();
    }

    float scale = (octile == 0) ? 0.25f : 1.0f;
#pragma unroll
    for (int mf = 0; mf < 4; mf++) {
        int oc = octile * 128 + (mw0 + mf) * 16 + g;
        float b0v = g_WB[oc];
        float b1v = g_WB[oc + 8];
        float* r0 = g_OUT + (size_t)(b * 640 + oc) * HW + y0 * WW;
        float* r1 = r0 + (size_t)8 * HW;
#pragma unroll
        for (int nf = 0; nf < 4; nf++) {
            int n = (n80 + nf) * 8 + tt * 2;
            float2 o0, o1;
            o0.x = (acc[mf][nf][0] + b0v) * scale;
            o0.y = (acc[mf][nf][1] + b0v) * scale;
            o1.x = (acc[mf][nf][2] + b1v) * scale;
            o1.y = (acc[mf][nf][3] + b1v) * scale;
            *(float2*)(r0 + n) = o0;
            *(float2*)(r1 + n) = o1;
        }
    }
}

// ---------------------------------------------------------------------------
// attn v5: 32x16 tile, 256 threads, 2 px/thread (horizontal pair).
// Halved per-thread register state -> target 3 CTAs/SM.
// 8-channel batched staging (proven), fragment fp16 output (proven).
// ---------------------------------------------------------------------------
__global__ __launch_bounds__(256) void attn_kernel(const float* __restrict__ dep_w,
                                                   const float* __restrict__ dep_b)
{
    __shared__ float s_dw[144][9];
    __shared__ float s_db[144];
    __shared__ float s_tile[8][18][36];

    int b    = blockIdx.z;
    int sn   = blockIdx.y;
    int sidx = sn >> 3, n = sn & 7;
    int tX   = (blockIdx.x & 3) * 32;
    int tY   = (blockIdx.x >> 2) * 16;
    int t    = threadIdx.x;
    int lx   = t & 15, ly = t >> 4;     // col-pair 0..15, row 0..15
    int px0  = tX + 2 * lx, py = tY + ly;

    for (int i = t; i < 144 * 9; i += 256) s_dw[i / 9][i % 9] = dep_w[i];
    if (t < 144) s_db[t] = dep_b[t];

    int kbase = (sidx == 0 ? 128 : 384) + n * 16;
    int vbase = kbase + 128;
    const float* Ob = g_OUT + (size_t)b * 640 * HW;

    float logit[2][9];
#pragma unroll
    for (int p = 0; p < 2; p++)
#pragma unroll
        for (int a = 0; a < 9; a++) logit[p][a] = 0.0f;

    // ---- phase K: logits (2 batches of 8 channels)
    for (int batch = 0; batch < 2; batch++) {
        __syncthreads();
#pragma unroll
        for (int dd = 0; dd < 8; dd++) {
            const float* P = Ob + (size_t)(kbase + batch * 8 + dd) * HW;
            for (int i = t; i < 18 * 34; i += 256) {
                int r = i / 34, c = i % 34;
                int yy = tY - 1 + r, xx = tX - 1 + c;
                float v = 0.0f;
                if (yy >= 0 && yy < HH && xx >= 0 && xx < WW) v = P[yy * WW + xx];
                s_tile[dd][r][c] = v;
            }
        }
        __syncthreads();
#pragma unroll 2
        for (int dd = 0; dd < 8; dd++) {
            int d = batch * 8 + dd;
            float tap[3][4];
#pragma unroll
            for (int yy = 0; yy < 3; yy++)
#pragma unroll
                for (int xx = 0; xx < 4; xx++)
                    tap[yy][xx] = s_tile[dd][ly + yy][2 * lx + xx];
            const float* Pq = Ob + (size_t)(n * 16 + d) * HW + py * WW + px0;
            float2 qv = *(const float2*)Pq;
#pragma unroll
            for (int a = 0; a < 9; a++) {
                const float* wp = s_dw[d * 9 + a];
                float w9[9];
#pragma unroll
                for (int k = 0; k < 9; k++) w9[k] = wp[k];
                float bsv = s_db[d * 9 + a];
#pragma unroll
                for (int p = 0; p < 2; p++) {
                    float kda = bsv;
#pragma unroll
                    for (int ky = 0; ky < 3; ky++)
#pragma unroll
                        for (int kx = 0; kx < 3; kx++)
                            kda += w9[ky * 3 + kx] * tap[ky][p + kx];
                    logit[p][a] += (p ? qv.y : qv.x) * kda;
                }
            }
        }
    }

    // ---- softmax
    float attnv[2][9];
#pragma unroll
    for (int p = 0; p < 2; p++) {
        float m = logit[p][0];
#pragma unroll
        for (int a = 1; a < 9; a++) m = fmaxf(m, logit[p][a]);
        float sum = 0.0f;
#pragma unroll
        for (int a = 0; a < 9; a++) { attnv[p][a] = __expf(logit[p][a] - m); sum += attnv[p][a]; }
        float inv = 1.0f / sum;
#pragma unroll
        for (int a = 0; a < 9; a++) attnv[p][a] *= inv;
    }

    // ---- phase V (2 batches of 8 channels)
    __half oh[2][16];
    for (int batch = 0; batch < 2; batch++) {
        __syncthreads();
#pragma unroll
        for (int dd = 0; dd < 8; dd++) {
            const float* P = Ob + (size_t)(vbase + batch * 8 + dd) * HW;
            for (int i = t; i < 18 * 34; i += 256) {
                int r = i / 34, c = i % 34;
                int yy = tY - 1 + r, xx = tX - 1 + c;
                float v = 0.0f;
                if (yy >= 0 && yy < HH && xx >= 0 && xx < WW) v = P[yy * WW + xx];
                s_tile[dd][r][c] = v;
            }
        }
        __syncthreads();
#pragma unroll 2
        for (int dd = 0; dd < 8; dd++) {
            int d = batch * 8 + dd;
            float tap[3][4];
#pragma unroll
            for (int yy = 0; yy < 3; yy++)
#pragma unroll
                for (int xx = 0; xx < 4; xx++)
                    tap[yy][xx] = s_tile[dd][ly + yy][2 * lx + xx];
            float outv[2] = {0.f, 0.f};
#pragma unroll
            for (int a = 0; a < 9; a++) {
                const float* wp = s_dw[d * 9 + a];
                float w9[9];
#pragma unroll
                for (int k = 0; k < 9; k++) w9[k] = wp[k];
                float bsv = s_db[d * 9 + a];
#pragma unroll
                for (int p = 0; p < 2; p++) {
                    float vda = bsv;
#pragma unroll
                    for (int ky = 0; ky < 3; ky++)
#pragma unroll
                        for (int kx = 0; kx < 3; kx++)
                            vda += w9[ky * 3 + kx] * tap[ky][p + kx];
                    outv[p] += attnv[p][a] * vda;
                }
            }
            const int h2 = d >> 3, rem = d & 7;
            const int j  = (rem >> 1) * 4 + h2 * 2 + (rem & 1);
#pragma unroll
            for (int p = 0; p < 2; p++) oh[p][j] = __float2half(outv[p]);
        }
    }

    __half* Adst = g_ATTh + (size_t)(b * 2 + sidx) * HW * 128;
#pragma unroll
    for (int p = 0; p < 2; p++) {
        int pix = py * WW + px0 + p;
        __half* dst = Adst + (size_t)pix * 128 + n * 16;
        *(uint4*)dst       = *(uint4*)&oh[p][0];
        *(uint4*)(dst + 8) = *(uint4*)&oh[p][8];
    }
}

// ---------------------------------------------------------------------------
// proj via mma: CTA = 128 oc x 128 px (one row), K=128. Writes d_out. UNCHANGED.
// ---------------------------------------------------------------------------
#define PROJ_SMEM 65536
__global__ __launch_bounds__(256) void proj_mma_kernel(
    const float* __restrict__ ppan_b, const float* __restrict__ pms_b,
    float* __restrict__ out)
{
    extern __shared__ char psm[];
    int t = threadIdx.x, w = t >> 5, lane = t & 31;
    int g = lane >> 2, tt = lane & 3;
    int mw0 = (w >> 2) * 4, n80 = (w & 3) * 4;
    int row = blockIdx.x, sidx = blockIdx.y, b = blockIdx.z;
    uint32_t sb = (uint32_t)__cvta_generic_to_shared(psm);

    const char* Asrc = (const char*)(g_WPh + (size_t)sidx * 16384);
#pragma unroll
    for (int j = 0; j < 8; j++) cp16(sb + t * 128 + j * 16, Asrc + t * 128 + j * 16);
    {
        int px = t >> 1;
        int kh = (t & 1) * 4;
        const char* Bsrc = (const char*)(g_ATTh +
            ((size_t)(b * 2 + sidx) * HW + row * 128 + px) * 128);
#pragma unroll
        for (int k16 = 0; k16 < 4; k16++) {
            uint32_t d = sb + 32768 + (kh + k16) * 4096 + px * 32;
            cp16(d,      Bsrc + (kh + k16) * 32);
            cp16(d + 16, Bsrc + (kh + k16) * 32 + 16);
        }
    }
    asm volatile("cp.async.commit_group;" ::: "memory");
    asm volatile("cp.async.wait_group 0;" ::: "memory");
    __syncthreads();

    float acc[4][4][4];
#pragma unroll
    for (int mf = 0; mf < 4; mf++)
#pragma unroll
        for (int nf = 0; nf < 4; nf++)
#pragma unroll
            for (int r = 0; r < 4; r++) acc[mf][nf][r] = 0.0f;

#pragma unroll
    for (int k16 = 0; k16 < 8; k16++) {
        uint32_t a[4][4];
#pragma unroll
        for (int mf = 0; mf < 4; mf++) {
            uint32_t addr = sb + k16 * 4096 + (mw0 + mf) * 512 + lane * 16;
            asm volatile("ld.shared.v4.u32 {%0,%1,%2,%3}, [%4];"
                : "=r"(a[mf][0]), "=r"(a[mf][1]), "=r"(a[mf][2]), "=r"(a[mf][3])
                : "r"(addr));
        }
        uint32_t b0[4], b1[4];
#pragma unroll
        for (int nf = 0; nf < 4; nf++) {
            uint32_t addr = sb + 32768 + k16 * 4096 + (((n80 + nf) * 8 + g) * 32) + tt * 8;
            asm volatile("ld.shared.v2.u32 {%0,%1}, [%2];"
                : "=r"(b0[nf]), "=r"(b1[nf]) : "r"(addr));
        }
#pragma unroll
        for (int mf = 0; mf < 4; mf++)
#pragma unroll
            for (int nf = 0; nf < 4; nf++)
                mma_f16(acc[mf][nf], a[mf], b0[nf], b1[nf]);
    }

    const float* bp = sidx ? pms_b : ppan_b;
    float* obase = out + (size_t)sidx * BB * DIM * HW;
#pragma unroll
    for (int mf = 0; mf < 4; mf++) {
        int oc = (mw0 + mf) * 16 + g;
        float b0v = bp[oc];
        float b1v = bp[oc + 8];
        float* r0 = obase + ((size_t)(b * DIM + oc)) * HW + row * WW;
        float* r1 = r0 + (size_t)8 * HW;
#pragma unroll
        for (int nf = 0; nf < 4; nf++) {
            int nn = (n80 + nf) * 8 + tt * 2;
            float2 o0, o1;
            o0.x = acc[mf][nf][0] + b0v;
            o0.y = acc[mf][nf][1] + b0v;
            o1.x = acc[mf][nf][2] + b1v;
            o1.y = acc[mf][nf][3] + b1v;
            *(float2*)(r0 + nn) = o0;
            *(float2*)(r1 + nn) = o1;
        }
    }
}

// ---------------------------------------------------------------------------
extern "C" void kernel_launch(void* const* d_in, const int* in_sizes, int n_in,
                              void* d_out, int out_size)
{
    const float* x        = (const float*)d_in[0];
    const float* ms       = (const float*)d_in[1];
    const float* lpan     = (const float*)d_in[2];
    const float* pan      = (const float*)d_in[3];
    const float* s        = (const float*)d_in[4];
    const float* q_w      = (const float*)d_in[5];
    const float* q_b      = (const float*)d_in[6];
    const float* k_pan_w  = (const float*)d_in[7];
    const float* k_pan_b  = (const float*)d_in[8];
    const float* v_pan_w  = (const float*)d_in[9];
    const float* v_pan_b  = (const float*)d_in[10];
    const float* kv_ms_w  = (const float*)d_in[11];
    const float* kv_ms_b  = (const float*)d_in[12];
    const float* dep_w    = (const float*)d_in[13];
    const float* dep_b    = (const float*)d_in[14];
    const float* ppan_w   = (const float*)d_in[15];
    const float* ppan_b   = (const float*)d_in[16];
    const float* pms_w    = (const float*)d_in[17];
    const float* pms_b    = (const float*)d_in[18];
    float* out = (float*)d_out;

    cudaFuncSetAttribute(conv_mma_kernel,
                         cudaFuncAttributeMaxDynamicSharedMemorySize, CONV_SMEM);
    cudaFuncSetAttribute(proj_mma_kernel,
                         cudaFuncAttributeMaxDynamicSharedMemorySize, PROJ_SMEM);

    dim3 xg(HW / 64, BB);
    build_xt_kernel<<<xg, 256>>>(x, ms, lpan, pan, s);
    prep_kernel<<<(PREP_TOTAL + 255) / 256, 256>>>(
        q_w, k_pan_w, v_pan_w, kv_ms_w, q_b, k_pan_b, v_pan_b, kv_ms_b,
        ppan_w, pms_w);

    dim3 cg(HH, 5, BB);
    conv_mma_kernel<<<cg, 256, CONV_SMEM>>>();

    dim3 ag(32, 16, BB);
    attn_kernel<<<ag, 256>>>(dep_w, dep_b);

    dim3 pj(HH, 2, BB);
    proj_mma_kernel<<<pj, 256, PROJ_SMEM>>>(ppan_b, pms_b, out);
}